// round 12
// baseline (speedup 1.0000x reference)
#include <cuda_runtime.h>
#include <math.h>

// Problem constants
#define SS 64
#define BB 32
#define DM 586
#define DE 583
#define NL 4
#define K1 17
#define CO1 16
#define CO2 8
#define P2LEN 38
#define CO3 32
#define T3 36
#define NV 128
#define MMW 31      // combined conv1+pool1+conv2+pool2 kernel length
#define XR 592      // smem x row stride (>= 586)
#define NCG 8       // ci groups
#define CIG 4       // ci per group
#define THR 320

// Scratch (no allocations allowed)
__device__ float g_rpart[SS*BB*2];            // per row: {sum, sumsq}
__device__ float g_c2part[SS*NCG*CO2*P2LEN];  // raw superconv partials [s][g][c8][q]
__device__ unsigned g_scnt[SS];               // per-s arrival counters (monotonic)

// ---------------------------------------------------------------------------
// Single fused kernel. grid = 512 (64 s x 8 ci-groups), block = 320.
// Per block:
//   phase 0: load w1 slice (own 4 ci) + w2 into smem (all threads).
//   phase 1: warps 0-7 gather 4 emb rows (tok hoisted, 2 warps/row) into smem
//            + per-row stats; warps 8-9 build this group's superconv weights
//            W[ci][mm][c8] (warp 8: c8 0-3, warp 9: c8 4-7; __syncwarp only).
//   phase 2: superconv (stride-15, K=31) partials -> g_c2part; stats -> g_rpart.
//   phase 3: last of 8 blocks per s (monotonic counter) runs the tail:
//            BN affine + o2 assembly -> conv3 -> proj(128x36) -> argmax.
// ---------------------------------------------------------------------------
__global__ void __launch_bounds__(THR)
kF(const int* __restrict__ tokens, const float* __restrict__ emb,
   const float* __restrict__ pos,
   const float* __restrict__ gamma, const float* __restrict__ beta,
   const float* __restrict__ w1, const float* __restrict__ b1,
   const float* __restrict__ w2, const float* __restrict__ b2,
   const float* __restrict__ w3, const float* __restrict__ b3,
   const float* __restrict__ wl, const float* __restrict__ bl,
   float* __restrict__ out) {
    int bx   = blockIdx.x;
    int s    = bx >> 3;
    int g    = bx & 7;
    int tid  = threadIdx.x;
    int wid  = tid >> 5;
    int lane = tid & 31;
    const float scale = sqrtf(586.0f);

    __shared__ float sw1g[CO1*CIG*K1];   // 1088: [co1][ci*17+k] (own 4 ci)
    __shared__ float sw2s[CO2*CO1];      // 128
    __shared__ float sS2[CIG*K1*CO2];    // 544: [(ci*17+k)*8 + c8]
    __shared__ float wsl[CIG*32*CO2];    // 1024: [(ci*32+mm)*8 + c8]
    __shared__ float xs[CIG*XR];         // 2368
    __shared__ float sst[16];            // gather warp partials {sum,sq}
    __shared__ int   sh_last;
    // tail-only
    __shared__ __align__(16) float wls[NV*T3];   // 4608
    __shared__ float bls[NV];
    __shared__ float o2s[CO2*P2LEN];             // 304
    __shared__ float o3s[CO3*T3];                // 1152
    __shared__ float sws[CO1];
    __shared__ float sa8[CO2], sb8[CO2];
    __shared__ float sAC[2];

    // ---------------- phase 0: stage weights ----------------
    for (int i = tid; i < CO1*CIG*K1; i += THR) {
        int co1 = i / (CIG*K1);
        int off = i - co1*(CIG*K1);
        sw1g[i] = w1[co1*(BB*K1) + g*(CIG*K1) + off];
    }
    if (tid < CO2*CO1) sw2s[tid] = w2[tid];
    __syncthreads();

    // ---------------- phase 1 ----------------
    if (wid < 8) {
        // gather: warp wid covers row ri = wid>>1, half part = wid&1
        int ri   = wid >> 1;
        int part = wid & 1;
        int b    = g*CIG + ri;
        int tok  = tokens[s*BB + b];
        const float* row = emb + (size_t)tok * DE;
        float sum = 0.f, sq = 0.f;
        int dbase = lane + 32*part;
        #pragma unroll
        for (int k = 0; k < 10; k++) {
            int d = dbase + 64*k;
            if (d < DE) {
                float v = row[d] * scale;
                xs[ri*XR + d] = v;
                sum += v; sq += v*v;
            }
        }
        if (part == 0 && lane < 3) {
            float v = pos[(s*BB + b)*3 + lane];
            xs[ri*XR + DE + lane] = v;
            sum += v; sq += v*v;
        }
        #pragma unroll
        for (int off = 16; off >= 1; off >>= 1) {
            sum += __shfl_down_sync(0xffffffffu, sum, off);
            sq  += __shfl_down_sync(0xffffffffu, sq,  off);
        }
        if (lane == 0) { sst[wid*2] = sum; sst[wid*2 + 1] = sq; }
    } else {
        // weight build for 4 c8 columns (warp 8: 0-3, warp 9: 4-7)
        int c8b = (wid - 8) * 4;
        // S2[(ci*17+k)*8+c8] = sum_co1 w2[c8][co1]*w1[co1][ci][k]
        for (int j = lane; j < CIG*K1*4; j += 32) {
            int c8 = c8b + (j & 3);
            int t  = j >> 2;
            int k  = t % K1;
            int ci = t / K1;
            float acc = 0.f;
            #pragma unroll
            for (int co1 = 0; co1 < CO1; co1++)
                acc += sw2s[c8*CO1 + co1] * sw1g[co1*(CIG*K1) + ci*K1 + k];
            sS2[(ci*K1 + k)*CO2 + c8] = acc;
        }
        __syncwarp();
        // W[(ci*32+mm)*8+c8] = (1/15) sum_{d=max(0,mm-16)}^{min(14,mm)} S2[ci][mm-d][c8]
        for (int j = lane; j < CIG*MMW*4; j += 32) {
            int c8 = c8b + (j & 3);
            int t  = j >> 2;
            int mm = t % MMW;
            int ci = t / MMW;
            int dlo = mm - (K1-1); if (dlo < 0) dlo = 0;
            int dhi = mm;          if (dhi > 14) dhi = 14;
            float acc = 0.f;
            for (int d = dlo; d <= dhi; d++)
                acc += sS2[(ci*K1 + (mm - d))*CO2 + c8];
            wsl[(ci*32 + mm)*CO2 + c8] = acc * (1.f/15.f);
        }
    }
    __syncthreads();

    // ---------------- phase 2: superconv partials + stats out ----------------
    if (tid < CO2*P2LEN) {
        int c8 = tid / P2LEN;
        int q  = tid - c8*P2LEN;
        float acc0 = 0.f, acc1 = 0.f;
        const float* xb = xs + 15*q;
        #pragma unroll
        for (int ci = 0; ci < CIG; ci++) {
            const float* xr = xb + ci*XR;
            const float* wp = wsl + ci*(32*CO2) + c8;
            #pragma unroll
            for (int mm = 0; mm < MMW; mm += 2) {
                acc0 += wp[mm*CO2] * xr[mm];
                if (mm + 1 < MMW) acc1 += wp[(mm+1)*CO2] * xr[mm+1];
            }
        }
        g_c2part[(s*NCG + g)*(CO2*P2LEN) + tid] = acc0 + acc1;
    }
    if (tid < CIG) {
        g_rpart[(s*BB + g*CIG + tid)*2 + 0] = sst[(2*tid)*2]     + sst[(2*tid+1)*2];
        g_rpart[(s*BB + g*CIG + tid)*2 + 1] = sst[(2*tid)*2 + 1] + sst[(2*tid+1)*2 + 1];
    }

    // ---------------- arrival: last of 8 blocks per s runs the tail ----------
    __threadfence();
    __syncthreads();
    if (tid == 0) {
        unsigned old = atomicAdd(&g_scnt[s], 1u);
        sh_last = ((old & 7u) == 7u) ? 1 : 0;
        __threadfence();
    }
    __syncthreads();
    if (!sh_last) return;

    // ---------------- tail ----------------
    // wsum1[co1] (full w1 rows, from global; L2-hot)
    for (int co1 = wid; co1 < CO1; co1 += 10) {
        float p = 0.f;
        for (int i = lane; i < BB*K1; i += 32) p += w1[co1*(BB*K1) + i];
        #pragma unroll
        for (int off = 16; off >= 1; off >>= 1)
            p += __shfl_down_sync(0xffffffffu, p, off);
        if (lane == 0) sws[co1] = p;
    }
    for (int i = tid; i < NV*T3; i += THR) wls[i] = wl[i];
    if (tid < NV) bls[tid] = bl[tid];
    __syncthreads();

    // BN affine (warp 0) + ws2a/ws2b (threads 0..7)
    if (wid == 0) {
        float su = __ldcg(&g_rpart[(s*BB + lane)*2 + 0]);
        float sq = __ldcg(&g_rpart[(s*BB + lane)*2 + 1]);
        #pragma unroll
        for (int off = 16; off >= 1; off >>= 1) {
            su += __shfl_down_sync(0xffffffffu, su, off);
            sq += __shfl_down_sync(0xffffffffu, sq, off);
        }
        if (lane == 0) {
            float invN = 1.f / (float)(BB*DM);
            float m = su * invN;
            float v = sq * invN - m*m;   // biased var, matches reference
            float A = 1.f, Cf = 0.f;
            #pragma unroll
            for (int l = 0; l < NL; l++) {
                float gg = gamma[l*SS + s];
                float bb = beta[l*SS + s];
                float inv = rsqrtf(v + 1e-5f);
                float a = gg * inv;
                float c = bb - a * m;
                A = a * A;
                Cf = a * Cf + c;
                m = bb;
                v = a * a * v;
            }
            sAC[0] = A; sAC[1] = Cf;
        }
    } else if (wid == 1 && lane < CO2) {
        float a = 0.f, bb = 0.f;
        #pragma unroll
        for (int co1 = 0; co1 < CO1; co1++) {
            float wv = sw2s[lane*CO1 + co1];
            a  += wv * sws[co1];
            bb += wv * b1[co1];
        }
        sa8[lane] = a;
        sb8[lane] = bb;
    }
    __syncthreads();

    float A = sAC[0], Cf = sAC[1];
    // o2 assembly: A*(sum of 8 partials) + Cf*ws2a + ws2b + b2
    {
        const float* pp = g_c2part + s*NCG*(CO2*P2LEN);
        for (int i = tid; i < CO2*P2LEN; i += THR) {
            int c8 = i / P2LEN;
            float p0 = __ldcg(&pp[i]),       p1 = __ldcg(&pp[304 + i]);
            float p2 = __ldcg(&pp[2*304+i]), p3 = __ldcg(&pp[3*304 + i]);
            float p4 = __ldcg(&pp[4*304+i]), p5 = __ldcg(&pp[5*304 + i]);
            float p6 = __ldcg(&pp[6*304+i]), p7 = __ldcg(&pp[7*304 + i]);
            float acc = ((p0 + p1) + (p2 + p3)) + ((p4 + p5) + (p6 + p7));
            o2s[i] = A*acc + Cf*sa8[c8] + sb8[c8] + b2[c8];
        }
    }
    __syncthreads();

    // conv3: (8,38) -> (32,36), K=3
    for (int i = tid; i < CO3*T3; i += THR) {
        int co = i / T3;
        int t  = i - co*T3;
        float acc = b3[co];
        #pragma unroll
        for (int c8 = 0; c8 < CO2; c8++) {
            const float* rr = o2s + c8*P2LEN + t;
            const float* w = w3 + (co*CO2 + c8)*3;
            acc += w[0]*rr[0] + w[1]*rr[1] + w[2]*rr[2];
        }
        o3s[i] = acc;
    }
    __syncthreads();

    // projection to 128 vocab + argmax (first-max semantics like jnp.argmax)
    if (tid < 256) {
        int c  = tid >> 3;   // channel 0..31
        int vl = tid & 7;    // vocab lane
        float orow[T3];
        #pragma unroll
        for (int k = 0; k < T3; k++) orow[k] = o3s[c*T3 + k];

        float bestv = -3.4e38f;
        int   besti = 0;
        #pragma unroll 2
        for (int i = 0; i < 16; i++) {
            int v = vl + 8*i;
            const float4* wr = (const float4*)(wls + v*T3);  // 36 floats = 9 float4
            float d0 = bls[v], d1 = 0.f;
            #pragma unroll
            for (int k4 = 0; k4 < 9; k4 += 2) {
                float4 w4 = wr[k4];
                d0 += orow[4*k4+0]*w4.x + orow[4*k4+1]*w4.y
                    + orow[4*k4+2]*w4.z + orow[4*k4+3]*w4.w;
            }
            #pragma unroll
            for (int k4 = 1; k4 < 9; k4 += 2) {
                float4 w4 = wr[k4];
                d1 += orow[4*k4+0]*w4.x + orow[4*k4+1]*w4.y
                    + orow[4*k4+2]*w4.z + orow[4*k4+3]*w4.w;
            }
            float d = d0 + d1;
            if (d > bestv) { bestv = d; besti = v; }  // strict > keeps first max in lane
        }
        #pragma unroll
        for (int off = 4; off >= 1; off >>= 1) {
            float ov = __shfl_down_sync(0xffffffffu, bestv, off);
            int   oi = __shfl_down_sync(0xffffffffu, besti, off);
            if (ov > bestv || (ov == bestv && oi < besti)) { bestv = ov; besti = oi; }
        }
        if (vl == 0) out[s*BB + c] = (float)besti;
    }
}

// ---------------------------------------------------------------------------
extern "C" void kernel_launch(void* const* d_in, const int* in_sizes, int n_in,
                              void* d_out, int out_size) {
    const int*   tokens = (const int*)  d_in[0];
    const float* emb    = (const float*)d_in[1];
    const float* pos    = (const float*)d_in[2];
    const float* gamma  = (const float*)d_in[3];
    const float* beta   = (const float*)d_in[4];
    const float* w1     = (const float*)d_in[5];
    const float* b1     = (const float*)d_in[6];
    const float* w2     = (const float*)d_in[7];
    const float* b2     = (const float*)d_in[8];
    const float* w3     = (const float*)d_in[9];
    const float* b3     = (const float*)d_in[10];
    const float* wl     = (const float*)d_in[11];
    const float* bl     = (const float*)d_in[12];
    float* out = (float*)d_out;

    kF<<<SS*NCG, THR>>>(tokens, emb, pos, gamma, beta, w1, b1,
                        w2, b2, w3, b3, wl, bl, out);
}

// round 13
// speedup vs baseline: 1.3774x; 1.3774x over previous
#include <cuda_runtime.h>
#include <math.h>

// Problem constants
#define SS 64
#define BB 32
#define DM 586
#define DE 583
#define NL 4
#define K1 17
#define CO1 16
#define CO2 8
#define P2LEN 38
#define CO3 32
#define T3 36
#define NV 128
#define MMW 31      // combined conv1+pool1+conv2+pool2 kernel length
#define XR 592      // smem x row stride (>= 586)

// Scratch (no allocations allowed)
__device__ float g_part[SS*2*2];              // per (s, half): {sum, sumsq}
__device__ float g_c2part[SS*8*CO2*P2LEN];    // raw superconv partials [s][g][c8][q]

// ---------------------------------------------------------------------------
// Kernel SC: one block per (s, half). 1024 threads.
//  phase 0: stage w1 slice (16 ci of this half, all co1) + w2 into smem.
//  phase 1: all 32 warps gather 16 emb rows (2 warps/row, 10-deep MLP) into
//           smem + per-row stats -> g_part (proven fast gather shape).
//  phase 2: build superconv weights W[cil][mm][c8] for this half's 16 ci
//           (S2 then pooled-window sums; redundant per block, trivial cost).
//  phase 3: superconv (stride-15, K=31) partials for 4 ci-subgroups
//           -> g_c2part[s][h*4+gg]. No g_x0 materialization at all.
// ---------------------------------------------------------------------------
__global__ void __launch_bounds__(1024)
kSC(const int* __restrict__ tokens, const float* __restrict__ emb,
    const float* __restrict__ pos, const float* __restrict__ w1,
    const float* __restrict__ w2) {
    extern __shared__ float dyn[];
    float* xs  = dyn;                    // 16*XR   = 9472 floats
    float* sw1 = dyn + 16*XR;            // 16*272  = 4352 (w1 slice [co1][cil*17+k])
    float* sS2 = sw1 + CO1*16*K1;        // 16*17*8 = 2176
    float* wsl = sS2 + 16*K1*CO2;        // 16*32*8 = 4096
    __shared__ float sw2s[CO2*CO1];      // 128
    __shared__ float sst[64];

    int bx   = blockIdx.x;
    int s    = bx >> 1;
    int h    = bx & 1;
    int tid  = threadIdx.x;
    int wid  = tid >> 5;
    int lane = tid & 31;
    const float scale = sqrtf(586.0f);

    // ---------------- phase 0: stage weights ----------------
    for (int i = tid; i < CO1*16*K1; i += 1024) {
        int co1 = i / (16*K1);
        int off = i - co1*(16*K1);
        sw1[i] = w1[co1*(BB*K1) + h*(16*K1) + off];
    }
    if (tid < CO2*CO1) sw2s[tid] = w2[tid];

    // ---------------- phase 1: gather + stats ----------------
    {
        int ri   = wid >> 1;           // local row 0..15
        int part = wid & 1;
        int b    = h*16 + ri;
        int tok  = tokens[s*BB + b];
        const float* row = emb + (size_t)tok * DE;
        float sum = 0.f, sq = 0.f;
        int dbase = lane + 32*part;
        #pragma unroll
        for (int k = 0; k < 10; k++) {
            int d = dbase + 64*k;
            if (d < DE) {
                float v = row[d] * scale;
                xs[ri*XR + d] = v;
                sum += v; sq += v*v;
            }
        }
        if (part == 0 && lane < 3) {
            float v = pos[(s*BB + b)*3 + lane];
            xs[ri*XR + DE + lane] = v;
            sum += v; sq += v*v;
        }
        #pragma unroll
        for (int off = 16; off >= 1; off >>= 1) {
            sum += __shfl_down_sync(0xffffffffu, sum, off);
            sq  += __shfl_down_sync(0xffffffffu, sq,  off);
        }
        if (lane == 0) { sst[wid] = sum; sst[32 + wid] = sq; }
    }
    __syncthreads();
    if (wid == 0) {
        float a = sst[lane];
        float c = sst[32 + lane];
        #pragma unroll
        for (int off = 16; off >= 1; off >>= 1) {
            a += __shfl_down_sync(0xffffffffu, a, off);
            c += __shfl_down_sync(0xffffffffu, c, off);
        }
        if (lane == 0) {
            g_part[(s*2 + h)*2 + 0] = a;
            g_part[(s*2 + h)*2 + 1] = c;
        }
    }

    // ---------------- phase 2: weight build ----------------
    // S2[(cil*17+k)*8+c8] = sum_co1 w2[c8][co1] * w1[co1][ci][k]
    for (int e = tid; e < 16*K1*CO2; e += 1024) {
        int c8 = e & 7;
        int t  = e >> 3;
        int k  = t % K1;
        int ci = t / K1;
        float acc = 0.f;
        #pragma unroll
        for (int co1 = 0; co1 < CO1; co1++)
            acc += sw2s[c8*CO1 + co1] * sw1[co1*(16*K1) + ci*K1 + k];
        sS2[(ci*K1 + k)*CO2 + c8] = acc;
    }
    __syncthreads();
    // W[(cil*32+mm)*8+c8] = (1/15) sum_{d=max(0,mm-16)}^{min(14,mm)} S2[cil][mm-d][c8]
    for (int e = tid; e < 16*MMW*CO2; e += 1024) {
        int c8 = e & 7;
        int t  = e >> 3;
        int mm = t % MMW;
        int ci = t / MMW;
        int dlo = mm - (K1-1); if (dlo < 0) dlo = 0;
        int dhi = mm;          if (dhi > 14) dhi = 14;
        float acc = 0.f;
        for (int d = dlo; d <= dhi; d++)
            acc += sS2[(ci*K1 + (mm - d))*CO2 + c8];
        wsl[(ci*32 + mm)*CO2 + c8] = acc * (1.f/15.f);
    }
    __syncthreads();

    // ---------------- phase 3: superconv partials ----------------
    // tasks: gg(4) x c8(8) x q(38) = 1216
    for (int t = tid; t < 4*CO2*P2LEN; t += 1024) {
        int q  = t % P2LEN;
        int rr = t / P2LEN;
        int c8 = rr & 7;
        int gg = rr >> 3;
        float acc0 = 0.f, acc1 = 0.f;
        const float* xb = xs + (gg*4)*XR + 15*q;
        #pragma unroll
        for (int ci = 0; ci < 4; ci++) {
            const float* xr = xb + ci*XR;
            const float* wp = wsl + (gg*4 + ci)*(32*CO2) + c8;
            #pragma unroll
            for (int mm = 0; mm < MMW; mm += 2) {
                acc0 += wp[mm*CO2] * xr[mm];
                if (mm + 1 < MMW) acc1 += wp[(mm+1)*CO2] * xr[mm+1];
            }
        }
        g_c2part[(s*8 + h*4 + gg)*(CO2*P2LEN) + c8*P2LEN + q] = acc0 + acc1;
    }
}

// ---------------------------------------------------------------------------
// Kernel D: fold BN affine, assemble o2 from 8 superconv partials, then
// conv3(K=3, 16 ch per block) -> proj(128x36) -> argmax.
// grid = 128 (64 s x 2 channel halves), block = 256.
// ---------------------------------------------------------------------------
__global__ void __launch_bounds__(256)
kD(const float* __restrict__ gamma, const float* __restrict__ beta,
   const float* __restrict__ w1, const float* __restrict__ b1,
   const float* __restrict__ w2, const float* __restrict__ b2,
   const float* __restrict__ w3, const float* __restrict__ b3,
   const float* __restrict__ wl, const float* __restrict__ bl,
   float* __restrict__ out) {
    int s    = blockIdx.x >> 1;
    int ch   = blockIdx.x & 1;
    int tid  = threadIdx.x;
    int wid  = tid >> 5;
    int lane = tid & 31;
    __shared__ __align__(16) float wls[NV*T3];       // 4608
    __shared__ float bls[NV];
    __shared__ float o2[CO2*P2LEN];                  // 304
    __shared__ float o3[16*T3];                      // 576
    __shared__ float sws[CO1];
    __shared__ float sw2s[CO2*CO1];
    __shared__ float sa8[CO2], sb8[CO2];

    // wsum1[co1] from w1 (L2-hot), 8 warps x 2 rows
    if (tid < CO2*CO1) sw2s[tid] = w2[tid];
    for (int co1 = wid; co1 < CO1; co1 += 8) {
        float p = 0.f;
        for (int i = lane; i < BB*K1; i += 32) p += w1[co1*(BB*K1) + i];
        #pragma unroll
        for (int off = 16; off >= 1; off >>= 1)
            p += __shfl_down_sync(0xffffffffu, p, off);
        if (lane == 0) sws[co1] = p;
    }
    for (int i = tid; i < NV*T3; i += 256) wls[i] = wl[i];
    if (tid < NV) bls[tid] = bl[tid];
    __syncthreads();

    if (tid < CO2) {
        float a = 0.f, bb = 0.f;
        #pragma unroll
        for (int co1 = 0; co1 < CO1; co1++) {
            float wv = sw2s[tid*CO1 + co1];
            a  += wv * sws[co1];
            bb += wv * b1[co1];
        }
        sa8[tid] = a;
        sb8[tid] = bb;
    }
    __syncthreads();

    // BN affine fold (redundant per thread; broadcast loads)
    float A, Cf;
    {
        float invN = 1.f / (float)(BB*DM);
        float ts = g_part[s*4 + 0] + g_part[s*4 + 2];
        float tq = g_part[s*4 + 1] + g_part[s*4 + 3];
        float m = ts * invN;
        float v = tq * invN - m*m;   // biased var, matches reference
        A = 1.f; Cf = 0.f;
        #pragma unroll
        for (int l = 0; l < NL; l++) {
            float gg = gamma[l*SS + s];
            float bb = beta[l*SS + s];
            float inv = rsqrtf(v + 1e-5f);
            float a = gg * inv;
            float c = bb - a * m;
            A = a * A;
            Cf = a * Cf + c;
            m = bb;
            v = a * a * v;
        }
    }

    // o2 assembly: A*(sum of 8 partials) + Cf*ws2a + ws2b + b2
    const float* pp = g_c2part + s*8*(CO2*P2LEN);
    for (int i = tid; i < CO2*P2LEN; i += 256) {
        int c8 = i / P2LEN;
        float acc = ((pp[i] + pp[304 + i]) + (pp[2*304 + i] + pp[3*304 + i]))
                  + ((pp[4*304 + i] + pp[5*304 + i]) + (pp[6*304 + i] + pp[7*304 + i]));
        o2[i] = A*acc + Cf*sa8[c8] + sb8[c8] + b2[c8];
    }
    __syncthreads();

    // conv3 for this half's 16 channels: (8,38) -> (16,36)
    for (int i = tid; i < 16*T3; i += 256) {
        int col = i / T3;
        int co  = ch*16 + col;
        int t   = i - col*T3;
        float acc = b3[co];
        #pragma unroll
        for (int c8 = 0; c8 < CO2; c8++) {
            const float* rr = o2 + c8*P2LEN + t;
            const float* w = w3 + (co*CO2 + c8)*3;
            acc += w[0]*rr[0] + w[1]*rr[1] + w[2]*rr[2];
        }
        o3[i] = acc;
    }
    __syncthreads();

    // projection to 128 vocab + argmax (first-max semantics like jnp.argmax)
    int c  = tid >> 4;   // local channel 0..15
    int vl = tid & 15;   // vocab lane
    float orow[T3];
    #pragma unroll
    for (int k = 0; k < T3; k++) orow[k] = o3[c*T3 + k];

    float bestv = -3.4e38f;
    int   besti = 0;
    #pragma unroll
    for (int i = 0; i < 8; i++) {
        int v = vl + 16*i;
        const float4* wr = (const float4*)(wls + v*T3);  // 36 floats = 9 float4
        float d0 = bls[v], d1 = 0.f;
        #pragma unroll
        for (int k4 = 0; k4 < 9; k4 += 2) {
            float4 w4 = wr[k4];
            d0 += orow[4*k4+0]*w4.x + orow[4*k4+1]*w4.y
                + orow[4*k4+2]*w4.z + orow[4*k4+3]*w4.w;
        }
        #pragma unroll
        for (int k4 = 1; k4 < 9; k4 += 2) {
            float4 w4 = wr[k4];
            d1 += orow[4*k4+0]*w4.x + orow[4*k4+1]*w4.y
                + orow[4*k4+2]*w4.z + orow[4*k4+3]*w4.w;
        }
        float d = d0 + d1;
        if (d > bestv) { bestv = d; besti = v; }  // strict > keeps first max in lane
    }
    #pragma unroll
    for (int off = 8; off >= 1; off >>= 1) {
        float ov = __shfl_down_sync(0xffffffffu, bestv, off);
        int   oi = __shfl_down_sync(0xffffffffu, besti, off);
        if (ov > bestv || (ov == bestv && oi < besti)) { bestv = ov; besti = oi; }
    }
    if (vl == 0) out[s*BB + ch*16 + c] = (float)besti;
}

// ---------------------------------------------------------------------------
extern "C" void kernel_launch(void* const* d_in, const int* in_sizes, int n_in,
                              void* d_out, int out_size) {
    const int*   tokens = (const int*)  d_in[0];
    const float* emb    = (const float*)d_in[1];
    const float* pos    = (const float*)d_in[2];
    const float* gamma  = (const float*)d_in[3];
    const float* beta   = (const float*)d_in[4];
    const float* w1     = (const float*)d_in[5];
    const float* b1     = (const float*)d_in[6];
    const float* w2     = (const float*)d_in[7];
    const float* b2     = (const float*)d_in[8];
    const float* w3     = (const float*)d_in[9];
    const float* b3     = (const float*)d_in[10];
    const float* wl     = (const float*)d_in[11];
    const float* bl     = (const float*)d_in[12];
    float* out = (float*)d_out;

    size_t shSC = (size_t)(16*XR + CO1*16*K1 + 16*K1*CO2 + 16*32*CO2) * sizeof(float); // 80384 B
    cudaFuncSetAttribute(kSC, cudaFuncAttributeMaxDynamicSharedMemorySize, (int)shSC);

    kSC<<<2*SS, 1024, shSC>>>(tokens, emb, pos, w1, w2);
    kD<<<128, 256>>>(gamma, beta, w1, b1, w2, b2, w3, b3, wl, bl, out);
}